// round 12
// baseline (speedup 1.0000x reference)
#include <cuda_runtime.h>
#include <cuda_bf16.h>
#include <cstdint>

// Problem constants (fixed by the reference)
#define B_SEG   16
#define D_F     128            // fine feature dim  (32 float4, 512 B/row)
#define D_C     256            // coarse feature dim (64 float4, 1024 B/row)
#define D_OUT   (D_C + D_F)    // 384

// One wave on 148 SMs at occupancy 8: 1184 CTAs, split by byte share.
#define NT_C    132            // coarse CTAs
#define NT_F    1052           // fine CTAs
#define NBLK    (NT_C + NT_F)

// 4KB units: fine = 8 rows x 32 float4 ; coarse = 4 rows x 64 float4.
// Both are 256 float4 = exactly one float4 per thread (offset == tid).
// CTA b owns units b, b+NT, b+2NT, ... -> the chip sweeps a contiguous
// ~17MB window at any instant (DRAM row-buffer locality), instead of
// 1184 scattered private streams.
#define UF4     256            // float4 per unit
#define UR_F    8              // fine rows per unit
#define UR_C    4              // coarse rows per unit

// Self-restoring device state (zero at module load; finalize resets it).
__device__ float        g_scratch[B_SEG * D_OUT];
__device__ unsigned int g_count = 0u;

__global__ __launch_bounds__(256, 8)
void pare_il_kernel(const float4* __restrict__ feats_c,
                    const float4* __restrict__ feats_f,
                    const int* __restrict__ lengths_c,
                    const int* __restrict__ lengths_f,
                    float* __restrict__ out,
                    int n_c, int n_f) {
    __shared__ float4 shred[256];
    __shared__ int    scum[B_SEG + 1];
    __shared__ bool   sdone;
    const int tid  = threadIdx.x;
    const int lane = tid & 31;

    const bool is_c = (blockIdx.x < NT_C);

    // parallel cumsum prologue (warp-redundant, no block barrier)
    {
        const int* L = is_c ? lengths_c : lengths_f;
        int v = (lane < B_SEG) ? __ldg(L + lane) : 0;
#pragma unroll
        for (int o = 1; o < B_SEG; o <<= 1) {
            int nn = __shfl_up_sync(0xFFFFFFFFu, v, o);
            if (lane >= o) v += nn;
        }
        if (lane < B_SEG) scum[lane + 1] = v;
        if (lane == 0)    scum[0] = 0;
        __syncwarp();
    }

    if (is_c) {
        // ================= coarse: units of 4 rows x 64 float4 =============
        const int bf   = blockIdx.x;
        const int nu   = n_c / UR_C;          // 8192 units
        const int c    = tid & 63;
        const int rloc = tid >> 6;            // row lane 0..3
        const float4* fp = feats_c + tid;

        int s = 0;
        while (scum[s + 1] <= bf * UR_C) ++s;
        int nb = scum[s + 1];

        float4 acc = make_float4(0.f, 0.f, 0.f, 0.f);

        for (int u0 = bf; u0 < nu; u0 += 4 * NT_C) {
            float4 v0, v1, v2, v3;
            const int u1 = u0 + NT_C, u2 = u0 + 2 * NT_C, u3 = u0 + 3 * NT_C;
            v0 = __ldcs(fp + (size_t)u0 * UF4);
            if (u1 < nu) v1 = __ldcs(fp + (size_t)u1 * UF4);
            if (u2 < nu) v2 = __ldcs(fp + (size_t)u2 * UF4);
            if (u3 < nu) v3 = __ldcs(fp + (size_t)u3 * UF4);

#pragma unroll
            for (int j = 0; j < 4; ++j) {
                const int uj = u0 + j * NT_C;
                if (uj >= nu) break;
                float4 v = (j == 0) ? v0 : (j == 1) ? v1 : (j == 2) ? v2 : v3;
                const int r0 = uj * UR_C;
                if (r0 + UR_C <= nb) {
                    acc.x += v.x; acc.y += v.y; acc.z += v.z; acc.w += v.w;
                } else {
                    int s2 = s; while (scum[s2 + 1] <= r0) ++s2;
                    int nb2 = scum[s2 + 1];
                    if (r0 + UR_C <= nb2) {
                        // clean segment change: flush old acc
                        shred[tid] = acc;
                        __syncthreads();
                        if (rloc == 0) {
                            float4 t = shred[c];
#pragma unroll
                            for (int k = 1; k < 4; ++k) {
                                float4 w = shred[k * 64 + c];
                                t.x += w.x; t.y += w.y; t.z += w.z; t.w += w.w;
                            }
                            float* o = g_scratch + s * D_OUT + c * 4;
                            atomicAdd(o + 0, t.x); atomicAdd(o + 1, t.y);
                            atomicAdd(o + 2, t.z); atomicAdd(o + 3, t.w);
                        }
                        __syncthreads();
                        acc = make_float4(v.x, v.y, v.z, v.w);
                        s = s2; nb = nb2;
                    } else {
                        // straddle unit (rare): per-thread direct atomics
                        int r = r0 + rloc;
                        int st = s2; while (scum[st + 1] <= r) ++st;
                        float* o = g_scratch + st * D_OUT + c * 4;
                        atomicAdd(o + 0, v.x); atomicAdd(o + 1, v.y);
                        atomicAdd(o + 2, v.z); atomicAdd(o + 3, v.w);
                    }
                }
            }
        }

        // final flush
        shred[tid] = acc;
        __syncthreads();
        if (rloc == 0) {
            float4 t = shred[c];
#pragma unroll
            for (int k = 1; k < 4; ++k) {
                float4 w = shred[k * 64 + c];
                t.x += w.x; t.y += w.y; t.z += w.z; t.w += w.w;
            }
            float* o = g_scratch + s * D_OUT + c * 4;
            atomicAdd(o + 0, t.x); atomicAdd(o + 1, t.y);
            atomicAdd(o + 2, t.z); atomicAdd(o + 3, t.w);
        }
        __syncthreads();
    } else {
        // ================= fine: units of 8 rows x 32 float4 ===============
        const int bf   = blockIdx.x - NT_C;
        const int nu   = n_f / UR_F;          // 65536 units
        const int c    = tid & 31;
        const int rloc = tid >> 5;            // row lane 0..7
        const float4* fp = feats_f + tid;

        int s = 0;
        while (scum[s + 1] <= bf * UR_F) ++s;
        int nb = scum[s + 1];

        float4 acc = make_float4(0.f, 0.f, 0.f, 0.f);

        for (int u0 = bf; u0 < nu; u0 += 4 * NT_F) {
            float4 v0, v1, v2, v3;
            const int u1 = u0 + NT_F, u2 = u0 + 2 * NT_F, u3 = u0 + 3 * NT_F;
            v0 = __ldcs(fp + (size_t)u0 * UF4);
            if (u1 < nu) v1 = __ldcs(fp + (size_t)u1 * UF4);
            if (u2 < nu) v2 = __ldcs(fp + (size_t)u2 * UF4);
            if (u3 < nu) v3 = __ldcs(fp + (size_t)u3 * UF4);

#pragma unroll
            for (int j = 0; j < 4; ++j) {
                const int uj = u0 + j * NT_F;
                if (uj >= nu) break;
                float4 v = (j == 0) ? v0 : (j == 1) ? v1 : (j == 2) ? v2 : v3;
                const int r0 = uj * UR_F;
                if (r0 + UR_F <= nb) {
                    acc.x += v.x; acc.y += v.y; acc.z += v.z; acc.w += v.w;
                } else {
                    int s2 = s; while (scum[s2 + 1] <= r0) ++s2;
                    int nb2 = scum[s2 + 1];
                    if (r0 + UR_F <= nb2) {
                        shred[tid] = acc;
                        __syncthreads();
                        if (rloc == 0) {
                            float4 t = shred[c];
#pragma unroll
                            for (int k = 1; k < 8; ++k) {
                                float4 w = shred[k * 32 + c];
                                t.x += w.x; t.y += w.y; t.z += w.z; t.w += w.w;
                            }
                            float* o = g_scratch + s * D_OUT + D_C + c * 4;
                            atomicAdd(o + 0, t.x); atomicAdd(o + 1, t.y);
                            atomicAdd(o + 2, t.z); atomicAdd(o + 3, t.w);
                        }
                        __syncthreads();
                        acc = make_float4(v.x, v.y, v.z, v.w);
                        s = s2; nb = nb2;
                    } else {
                        int r = r0 + rloc;
                        int st = s2; while (scum[st + 1] <= r) ++st;
                        float* o = g_scratch + st * D_OUT + D_C + c * 4;
                        atomicAdd(o + 0, v.x); atomicAdd(o + 1, v.y);
                        atomicAdd(o + 2, v.z); atomicAdd(o + 3, v.w);
                    }
                }
            }
        }

        shred[tid] = acc;
        __syncthreads();
        if (rloc == 0) {
            float4 t = shred[c];
#pragma unroll
            for (int k = 1; k < 8; ++k) {
                float4 w = shred[k * 32 + c];
                t.x += w.x; t.y += w.y; t.z += w.z; t.w += w.w;
            }
            float* o = g_scratch + s * D_OUT + D_C + c * 4;
            atomicAdd(o + 0, t.x); atomicAdd(o + 1, t.y);
            atomicAdd(o + 2, t.z); atomicAdd(o + 3, t.w);
        }
        __syncthreads();
    }

    // ---- last block to finish performs finalize + state reset ----
    if (tid == 0) {
        __threadfence();
        unsigned int old = atomicAdd(&g_count, 1u);
        sdone = (old == gridDim.x - 1);
    }
    __syncthreads();

    if (sdone) {
        __threadfence();  // make all blocks' atomics visible
        for (int i = tid; i < B_SEG * D_OUT; i += 256) {
            int b = i / D_OUT;
            int d = i - b * D_OUT;
            int len = (d < D_C) ? lengths_c[b] : lengths_f[b];
            out[i] = g_scratch[i] / (float)len;
            g_scratch[i] = 0.0f;
        }
        __syncthreads();
        if (tid == 0) g_count = 0u;
    }
}

// ---------------------------------------------------------------------------
extern "C" void kernel_launch(void* const* d_in, const int* in_sizes, int n_in,
                              void* d_out, int out_size) {
    const float* feats_f   = (const float*)d_in[0];   // [524288, 128]
    const float* feats_c   = (const float*)d_in[1];   // [32768, 256]
    const int*   lengths_f = (const int*)d_in[2];     // [16]
    const int*   lengths_c = (const int*)d_in[3];     // [16]
    float* out = (float*)d_out;                       // [16, 384]

    const int n_f = in_sizes[0] / D_F;   // total fine rows
    const int n_c = in_sizes[1] / D_C;   // total coarse rows

    pare_il_kernel<<<NBLK, 256>>>((const float4*)feats_c,
                                  (const float4*)feats_f,
                                  lengths_c, lengths_f, out, n_c, n_f);
}

// round 13
// speedup vs baseline: 2.4665x; 2.4665x over previous
#include <cuda_runtime.h>
#include <cuda_bf16.h>
#include <cstdint>

// Problem constants (fixed by the reference)
#define B_SEG   16
#define D_F     128            // fine feature dim  (32 float4)
#define D_C     256            // coarse feature dim (64 float4)
#define D_OUT   (D_C + D_F)    // 384

// Exactly one full wave on 148 SMs at occupancy 8: 148*8 = 1184 CTAs.
// Byte-balanced split: coarse tile ~248KB, fine tile ~249KB.
#define NT_C    132            // coarse tiles
#define NT_F    1052           // fine tiles
#define NBLK    (NT_C + NT_F)  // 1184

// Self-restoring device state (zero at module load; each segment's last
// contributor finalizes that segment and resets its state, so every graph
// replay sees zeros again).
__device__ float        g_scratch[B_SEG * D_OUT];
__device__ unsigned int g_segcnt[B_SEG];

// Tile index containing global row r for a tiling of n rows into NT tiles
// with boundaries floor(t*n/NT).
__device__ __forceinline__ int tile_of(int r, int NT, long long n) {
    return (int)(((long long)(r + 1) * NT - 1) / n);
}

__global__ __launch_bounds__(256, 8)
void pare_fused_kernel(const float4* __restrict__ feats_c,
                       const float4* __restrict__ feats_f,
                       const int* __restrict__ lengths_c,
                       const int* __restrict__ lengths_f,
                       float* __restrict__ out,
                       int n_c, int n_f) {
    __shared__ float4 shred[256];
    __shared__ int    scumC[B_SEG + 1];
    __shared__ int    scumF[B_SEG + 1];
    __shared__ bool   sfin;
    const int tid  = threadIdx.x;
    const int lane = tid & 31;

    const bool is_c = (blockIdx.x < NT_C);

    // ---- parallel prologue: both cumsums via warp shfl scans ----
    {
        int vc = (lane < B_SEG) ? __ldg(lengths_c + lane) : 0;
        int vf = (lane < B_SEG) ? __ldg(lengths_f + lane) : 0;
#pragma unroll
        for (int o = 1; o < B_SEG; o <<= 1) {
            int nc2 = __shfl_up_sync(0xFFFFFFFFu, vc, o);
            int nf2 = __shfl_up_sync(0xFFFFFFFFu, vf, o);
            if (lane >= o) { vc += nc2; vf += nf2; }
        }
        if (lane < B_SEG) { scumC[lane + 1] = vc; scumF[lane + 1] = vf; }
        if (lane == 0)    { scumC[0] = 0;        scumF[0] = 0; }
        __syncwarp();
    }

    const int* scum = is_c ? scumC : scumF;

    // tile row range (byte-balanced, perfect-wave grid)
    int r0, r1;
    if (is_c) {
        int t = blockIdx.x;
        r0 = (int)(((long long)t)       * n_c / NT_C);
        r1 = (int)(((long long)(t + 1)) * n_c / NT_C);
    } else {
        int t = blockIdx.x - NT_C;
        r0 = (int)(((long long)t)       * n_f / NT_F);
        r1 = (int)(((long long)(t + 1)) * n_f / NT_F);
    }

    const int c     = is_c ? (tid & 63) : (tid & 31);
    const int rr    = is_c ? (tid >> 6) : (tid >> 5);
    const int lanes = is_c ? 4 : 8;
    const int fcols = is_c ? 64 : 32;
    const int obase = is_c ? 0 : D_C;
    const float4* base = (is_c ? feats_c : feats_f) + c;

    int s = 0;
    while (scum[s + 1] <= r0) ++s;

    while (r0 < r1) {
        int e = scum[s + 1]; if (e > r1) e = r1;

        float4 acc = make_float4(0.f, 0.f, 0.f, 0.f);
#pragma unroll 4
        for (int r = r0 + rr; r < e; r += lanes) {
            float4 v = __ldcs(base + (size_t)r * fcols);
            acc.x += v.x; acc.y += v.y; acc.z += v.z; acc.w += v.w;
        }

        // ---- block flush of this segment run ----
        shred[tid] = acc;
        __syncthreads();
        if (rr == 0) {
            float4 t = shred[c];
            for (int k = 1; k < lanes; ++k) {
                float4 w = shred[k * fcols + c];
                t.x += w.x; t.y += w.y; t.z += w.z; t.w += w.w;
            }
            float* o = g_scratch + s * D_OUT + obase + c * 4;
            atomicAdd(o + 0, t.x);
            atomicAdd(o + 1, t.y);
            atomicAdd(o + 2, t.z);
            atomicAdd(o + 3, t.w);
        }
        __threadfence();   // release our sums before the counter bump
        __syncthreads();

        // ---- per-segment completion counter; last contributor finalizes ----
        if (tid == 0) {
            // number of tiles (both tensors) contributing to segment s
            int cA = tile_of(scumC[s + 1] - 1, NT_C, n_c)
                   - tile_of(scumC[s],         NT_C, n_c) + 1;
            int cB = tile_of(scumF[s + 1] - 1, NT_F, n_f)
                   - tile_of(scumF[s],         NT_F, n_f) + 1;
            unsigned int expected = (unsigned int)(cA + cB);
            unsigned int old = atomicAdd(&g_segcnt[s], 1u);
            sfin = (old == expected - 1u);
        }
        __syncthreads();

        if (sfin) {
            __threadfence();   // acquire: all contributors' atomics visible
            for (int i = tid; i < D_OUT; i += 256) {
                int len = (i < D_C) ? (scumC[s + 1] - scumC[s])
                                    : (scumF[s + 1] - scumF[s]);
                float v = __ldcg(&g_scratch[s * D_OUT + i]);
                out[s * D_OUT + i] = v / (float)len;
                g_scratch[s * D_OUT + i] = 0.0f;
            }
            if (tid == 0) g_segcnt[s] = 0u;
        }
        __syncthreads();

        r0 = e; ++s;
    }
}

// ---------------------------------------------------------------------------
extern "C" void kernel_launch(void* const* d_in, const int* in_sizes, int n_in,
                              void* d_out, int out_size) {
    const float* feats_f   = (const float*)d_in[0];   // [524288, 128]
    const float* feats_c   = (const float*)d_in[1];   // [32768, 256]
    const int*   lengths_f = (const int*)d_in[2];     // [16]
    const int*   lengths_c = (const int*)d_in[3];     // [16]
    float* out = (float*)d_out;                       // [16, 384]

    const int n_f = in_sizes[0] / D_F;   // total fine rows
    const int n_c = in_sizes[1] / D_C;   // total coarse rows

    pare_fused_kernel<<<NBLK, 256>>>((const float4*)feats_c,
                                     (const float4*)feats_f,
                                     lengths_c, lengths_f, out, n_c, n_f);
}

// round 14
// speedup vs baseline: 2.5733x; 1.0433x over previous
#include <cuda_runtime.h>
#include <cuda_bf16.h>
#include <cstdint>

// Problem constants (fixed by the reference)
#define B_SEG   16
#define D_F     128            // fine feature dim  (32 float4)
#define D_C     256            // coarse feature dim (64 float4)
#define D_OUT   (D_C + D_F)    // 384

// Exactly one full wave on 148 SMs at occupancy 8: 148*8 = 1184 CTAs.
// Byte-balanced split: coarse tile ~248KB, fine tile ~249KB.
#define NT_C    132            // coarse tiles
#define NT_F    1052           // fine tiles
#define NBLK    (NT_C + NT_F)  // 1184

// Self-restoring device state (zero at module load; each segment's last
// contributor finalizes that segment and resets its state, so every graph
// replay sees zeros again).
__device__ float        g_scratch[B_SEG * D_OUT];
__device__ unsigned int g_segcnt[B_SEG];

// Tile index containing global row r for a tiling of n rows into NT tiles
// with boundaries floor(t*n/NT).
__device__ __forceinline__ int tile_of(int r, int NT, long long n) {
    return (int)(((long long)(r + 1) * NT - 1) / n);
}

// ---------------------------------------------------------------------------
// Specialized work loop: FCOLS float4 per row, LANES row lanes, OBASE output
// column offset. All addressing/strides are compile-time constants.
// ---------------------------------------------------------------------------
template<int FCOLS, int LANES, int OBASE>
__device__ __forceinline__
void run_path(const float4* __restrict__ feats,
              float* __restrict__ out,
              const int* scumC, const int* scumF,
              float4* shred, bool* sfin,
              int r0, int r1, int n_c, int n_f) {
    const int tid = threadIdx.x;
    const int c   = tid % FCOLS;
    const int rr  = tid / FCOLS;
    const int* scum = (OBASE == 0) ? scumC : scumF;
    const float4* base = feats + c;

    int s = 0;
    while (scum[s + 1] <= r0) ++s;

    while (r0 < r1) {
        int e = scum[s + 1]; if (e > r1) e = r1;

        float4 acc = make_float4(0.f, 0.f, 0.f, 0.f);
#pragma unroll 4
        for (int r = r0 + rr; r < e; r += LANES) {
            float4 v = __ldcs(base + (size_t)r * FCOLS);
            acc.x += v.x; acc.y += v.y; acc.z += v.z; acc.w += v.w;
        }

        // ---- block flush of this segment run ----
        shred[tid] = acc;
        __syncthreads();
        if (rr == 0) {
            float4 t = shred[c];
#pragma unroll
            for (int k = 1; k < LANES; ++k) {
                float4 w = shred[k * FCOLS + c];
                t.x += w.x; t.y += w.y; t.z += w.z; t.w += w.w;
            }
            float* o = g_scratch + s * D_OUT + OBASE + c * 4;
            atomicAdd(o + 0, t.x);
            atomicAdd(o + 1, t.y);
            atomicAdd(o + 2, t.z);
            atomicAdd(o + 3, t.w);
        }
        __threadfence();   // release our sums before the counter bump
        __syncthreads();

        // ---- per-segment completion counter; last contributor finalizes ----
        if (tid == 0) {
            int cA = tile_of(scumC[s + 1] - 1, NT_C, n_c)
                   - tile_of(scumC[s],         NT_C, n_c) + 1;
            int cB = tile_of(scumF[s + 1] - 1, NT_F, n_f)
                   - tile_of(scumF[s],         NT_F, n_f) + 1;
            unsigned int expected = (unsigned int)(cA + cB);
            unsigned int old = atomicAdd(&g_segcnt[s], 1u);
            *sfin = (old == expected - 1u);
        }
        __syncthreads();

        if (*sfin) {
            __threadfence();   // acquire: all contributors' atomics visible
            for (int i = tid; i < D_OUT; i += 256) {
                int len = (i < D_C) ? (scumC[s + 1] - scumC[s])
                                    : (scumF[s + 1] - scumF[s]);
                float v = __ldcg(&g_scratch[s * D_OUT + i]);
                out[s * D_OUT + i] = v / (float)len;
                g_scratch[s * D_OUT + i] = 0.0f;
            }
            if (tid == 0) g_segcnt[s] = 0u;
        }
        __syncthreads();

        r0 = e; ++s;
    }
}

__global__ __launch_bounds__(256, 8)
void pare_fused_kernel(const float4* __restrict__ feats_c,
                       const float4* __restrict__ feats_f,
                       const int* __restrict__ lengths_c,
                       const int* __restrict__ lengths_f,
                       float* __restrict__ out,
                       int n_c, int n_f) {
    __shared__ float4 shred[256];
    __shared__ int    scumC[B_SEG + 1];
    __shared__ int    scumF[B_SEG + 1];
    __shared__ bool   sfin;
    const int tid  = threadIdx.x;
    const int lane = tid & 31;

    // ---- parallel prologue: both cumsums via warp shfl scans ----
    {
        int vc = (lane < B_SEG) ? __ldg(lengths_c + lane) : 0;
        int vf = (lane < B_SEG) ? __ldg(lengths_f + lane) : 0;
#pragma unroll
        for (int o = 1; o < B_SEG; o <<= 1) {
            int nc2 = __shfl_up_sync(0xFFFFFFFFu, vc, o);
            int nf2 = __shfl_up_sync(0xFFFFFFFFu, vf, o);
            if (lane >= o) { vc += nc2; vf += nf2; }
        }
        if (lane < B_SEG) { scumC[lane + 1] = vc; scumF[lane + 1] = vf; }
        if (lane == 0)    { scumC[0] = 0;        scumF[0] = 0; }
        __syncwarp();
    }

    if (blockIdx.x < NT_C) {
        const int t = blockIdx.x;
        int r0 = (int)(((long long)t)       * n_c / NT_C);
        int r1 = (int)(((long long)(t + 1)) * n_c / NT_C);
        run_path<64, 4, 0>(feats_c, out, scumC, scumF, shred, &sfin,
                           r0, r1, n_c, n_f);
    } else {
        const int t = blockIdx.x - NT_C;
        int r0 = (int)(((long long)t)       * n_f / NT_F);
        int r1 = (int)(((long long)(t + 1)) * n_f / NT_F);
        run_path<32, 8, D_C>(feats_f, out, scumC, scumF, shred, &sfin,
                             r0, r1, n_c, n_f);
    }
}

// ---------------------------------------------------------------------------
extern "C" void kernel_launch(void* const* d_in, const int* in_sizes, int n_in,
                              void* d_out, int out_size) {
    const float* feats_f   = (const float*)d_in[0];   // [524288, 128]
    const float* feats_c   = (const float*)d_in[1];   // [32768, 256]
    const int*   lengths_f = (const int*)d_in[2];     // [16]
    const int*   lengths_c = (const int*)d_in[3];     // [16]
    float* out = (float*)d_out;                       // [16, 384]

    const int n_f = in_sizes[0] / D_F;   // total fine rows
    const int n_c = in_sizes[1] / D_C;   // total coarse rows

    pare_fused_kernel<<<NBLK, 256>>>((const float4*)feats_c,
                                     (const float4*)feats_f,
                                     lengths_c, lengths_f, out, n_c, n_f);
}